// round 14
// baseline (speedup 1.0000x reference)
#include <cuda_runtime.h>
#include <cuda_bf16.h>
#include <cuda_fp16.h>
#include <cstdint>

#define NB 4
#define NPIX 4096
#define CDIM 256
#define CK 32
#define TOTPIX (NB*NPIX)
#define LOG2E 1.4426950408889634f
#define SHIFT 28.853900817779268f   // 20 * log2(e)

__device__ __half g_k[TOTPIX*CK];                   // keys fp16
__device__ __half g_q[TOTPIX*CK];                   // queries fp16, pre-scaled log2e
__device__ __nv_bfloat16 g_hT[(size_t)CDIM*TOTPIX]; // values bf16, channel-major
__device__ __half g_xh[(size_t)TOTPIX*CDIM];        // x as fp16 [px][256]
__device__ __half g_wT[320*CDIM];                   // [col][256] fp16 (Wg pre-scaled)

__device__ __forceinline__ uint32_t bf2u32(float a, float b) {
    __nv_bfloat162 h = __floats2bfloat162_rn(a, b);
    return *reinterpret_cast<uint32_t*>(&h);
}
__device__ __forceinline__ uint32_t smem_u32(const void* p) {
    uint32_t r;
    asm("{ .reg .u64 t; cvta.to.shared.u64 t, %1; cvt.u32.u64 %0, t; }" : "=r"(r) : "l"(p));
    return r;
}
__device__ __forceinline__ float ex2(float x) {
    float y; asm("ex2.approx.f32 %0,%1;" : "=f"(y) : "f"(x)); return y;
}
__device__ __forceinline__ void mma_bf16(float* c, const uint32_t* a, uint32_t b0, uint32_t b1) {
    asm volatile(
        "mma.sync.aligned.m16n8k16.row.col.f32.bf16.bf16.f32 "
        "{%0,%1,%2,%3},{%4,%5,%6,%7},{%8,%9},{%0,%1,%2,%3};"
        : "+f"(c[0]), "+f"(c[1]), "+f"(c[2]), "+f"(c[3])
        : "r"(a[0]), "r"(a[1]), "r"(a[2]), "r"(a[3]), "r"(b0), "r"(b1));
}
__device__ __forceinline__ void mma_f16(float* c, const uint32_t* a, uint32_t b0, uint32_t b1) {
    asm volatile(
        "mma.sync.aligned.m16n8k16.row.col.f32.f16.f16.f32 "
        "{%0,%1,%2,%3},{%4,%5,%6,%7},{%8,%9},{%0,%1,%2,%3};"
        : "+f"(c[0]), "+f"(c[1]), "+f"(c[2]), "+f"(c[3])
        : "r"(a[0]), "r"(a[1]), "r"(a[2]), "r"(a[3]), "r"(b0), "r"(b1));
}
__device__ __forceinline__ void ldsm4(uint32_t addr, uint32_t* r) {
    asm volatile("ldmatrix.sync.aligned.m8n8.x4.shared.b16 {%0,%1,%2,%3},[%4];"
        : "=r"(r[0]), "=r"(r[1]), "=r"(r[2]), "=r"(r[3]) : "r"(addr));
}
__device__ __forceinline__ void cpa16(uint32_t dst, const void* src) {
    asm volatile("cp.async.cg.shared.global [%0],[%1],16;" :: "r"(dst), "l"(src) : "memory");
}
#define CPA_COMMIT() asm volatile("cp.async.commit_group;" ::: "memory")
#define CPA_WAIT(n)  asm volatile("cp.async.wait_group %0;" :: "n"(n) : "memory")

// swizzled layouts (stride = row bytes; swizzle bits [4:6] by row&7)
__device__ __forceinline__ uint32_t addrA(uint32_t base, int rbase, int kb, int stride, int lane) {
    int g = lane >> 3, lr = lane & 7;
    int r = rbase + lr + (g & 1) * 8;
    int kk = kb + (g & 2) * 8;
    return base + r * stride + (kk ^ ((r & 7) << 4));
}
__device__ __forceinline__ uint32_t addrB(uint32_t base, int rbase, int kb, int stride, int lane) {
    int g = lane >> 3, lr = lane & 7;
    int r = rbase + lr + (g & 2) * 4;
    int kk = kb + (g & 1) * 16;
    return base + r * stride + (kk ^ ((r & 7) << 4));
}
// packed 64B-rows (2 rows per 128B frame) layouts (Q, K) -- conflict-free
__device__ __forceinline__ uint32_t addrA_pk(uint32_t base, int rbase, int kb, int lane) {
    int g = lane >> 3, lr = lane & 7;
    int r = rbase + lr + (g & 1) * 8;
    int kk = kb + (g & 2) * 8;
    return base + (r >> 1)*128 + (r & 1)*64 + kk;
}
__device__ __forceinline__ uint32_t addrB_pk(uint32_t base, int rbase, int kb, int lane) {
    int g = lane >> 3, lr = lane & 7;
    int r = rbase + lr + (g & 2) * 4;
    int kk = kb + (g & 1) * 16;
    return base + (r >> 1)*128 + (r & 1)*64 + kk;
}

// ============================================================================
// Pre-kernel A: weight transpose -> g_wT[col][256] fp16
// ============================================================================
__global__ __launch_bounds__(256) void wsplit_kernel(
    const float* __restrict__ Wf, const float* __restrict__ Wg,
    const float* __restrict__ Wh)
{
    const int col = blockIdx.x;
    const int k = threadIdx.x;
    float w;
    if (col < 256)      w = Wh[k*256 + col];
    else if (col < 288) w = Wf[k*32 + (col-256)];
    else                w = Wg[k*32 + (col-288)] * LOG2E;
    g_wT[col*CDIM + k] = __float2half_rn(w);
}

// ============================================================================
// Pre-kernel B: x f32 -> fp16  g_xh[px][256]
// ============================================================================
__global__ __launch_bounds__(256) void xsplit_kernel(const float* __restrict__ x)
{
    const size_t gid = (size_t)blockIdx.x * 256 + threadIdx.x;
    const float4 v0 = *(const float4*)(x + gid*8);
    const float4 v1 = *(const float4*)(x + gid*8 + 4);
    __half2 h[4];
    h[0] = __floats2half2_rn(v0.x, v0.y);
    h[1] = __floats2half2_rn(v0.z, v0.w);
    h[2] = __floats2half2_rn(v1.x, v1.y);
    h[3] = __floats2half2_rn(v1.z, v1.w);
    *(uint4*)(g_xh + gid*8) = *(const uint4*)h;
}

// ============================================================================
// Projection GEMM: C[16384,320] = x_f16 @ g_wT^T, K=256 in 2 chunks.
// ============================================================================
#define PJ_AB   32768u
#define PJ_BB   16384u
#define PJ_SMEM (2*PJ_AB + 2*PJ_BB)

__device__ __forceinline__ void pj_copy(uint32_t smb, int t, int rows0, int c0, int n)
{
    const uint32_t ab = smb + (uint32_t)(n & 1)*PJ_AB;
    const uint32_t bb = smb + 2*PJ_AB + (uint32_t)(n & 1)*PJ_BB;
    {
        const int r = t >> 1, half = t & 1;
        const __half* src = g_xh + (size_t)(rows0 + r)*CDIM + n*128;
        #pragma unroll
        for (int i = 0; i < 8; i++) {
            int p = half*8 + i;
            cpa16(ab + r*256 + ((p*16) ^ ((r & 7) << 4)), src + p*8);
        }
    }
    {
        const int c = t >> 2, q = t & 3;
        const __half* src = g_wT + (size_t)(c0 + c)*CDIM + n*128;
        #pragma unroll
        for (int i = 0; i < 4; i++) {
            int p = q*4 + i;
            cpa16(bb + c*256 + ((p*16) ^ ((c & 7) << 4)), src + p*8);
        }
    }
}

__global__ __launch_bounds__(256, 2) void proj_kernel(
    const float* __restrict__ bfp, const float* __restrict__ bgp,
    const float* __restrict__ bhp)
{
    extern __shared__ char sm[];
    const uint32_t smb = smem_u32(sm);
    const int t = threadIdx.x;
    const int w = t >> 5;
    const int lane = t & 31;
    const int rows0 = blockIdx.x * 128;
    const int c0 = blockIdx.y * 64;
    const int rs = (w & 3) * 32;
    const int cs = (w >> 2) * 32;

    float acc[2][4][4];
    #pragma unroll
    for (int m = 0; m < 2; m++)
        #pragma unroll
        for (int n = 0; n < 4; n++)
            { acc[m][n][0]=0.f; acc[m][n][1]=0.f; acc[m][n][2]=0.f; acc[m][n][3]=0.f; }

    pj_copy(smb, t, rows0, c0, 0);
    CPA_COMMIT();
    pj_copy(smb, t, rows0, c0, 1);
    CPA_COMMIT();
    CPA_WAIT(1);
    __syncthreads();

    #pragma unroll
    for (int n = 0; n < 2; n++) {
        if (n == 1) { CPA_WAIT(0); __syncthreads(); }
        const uint32_t ab = smb + (uint32_t)(n & 1)*PJ_AB;
        const uint32_t bb = smb + 2*PJ_AB + (uint32_t)(n & 1)*PJ_BB;
        #pragma unroll
        for (int k16 = 0; k16 < 8; k16++) {
            uint32_t a0[4], a1[4];
            ldsm4(addrA(ab, rs,      k16*32, 256, lane), a0);
            ldsm4(addrA(ab, rs + 16, k16*32, 256, lane), a1);
            #pragma unroll
            for (int n16 = 0; n16 < 2; n16++) {
                uint32_t B[4];
                ldsm4(addrB(bb, cs + n16*16, k16*32, 256, lane), B);
                mma_f16(acc[0][n16*2],   a0, B[0], B[1]);
                mma_f16(acc[0][n16*2+1], a0, B[2], B[3]);
                mma_f16(acc[1][n16*2],   a1, B[0], B[1]);
                mma_f16(acc[1][n16*2+1], a1, B[2], B[3]);
            }
        }
    }

    #pragma unroll
    for (int n = 0; n < 4; n++) {
        const int cA = cs + n*8 + (lane & 3)*2;
        #pragma unroll
        for (int half = 0; half < 2; half++) {
            const int gc = c0 + cA + half;
            float bias;
            if (gc < 256)      bias = bhp[gc];
            else if (gc < 288) bias = bfp[gc-256];
            else               bias = bgp[gc-288] * LOG2E;
            #pragma unroll
            for (int m = 0; m < 2; m++) {
                #pragma unroll
                for (int eh = 0; eh < 2; eh++) {
                    const int r = rs + m*16 + (lane >> 2) + eh*8;
                    const int px = rows0 + r;
                    float v = acc[m][n][eh*2 + half] + bias;
                    if (gc < 256) {
                        g_hT[(size_t)gc*TOTPIX + px] = __float2bfloat16_rn(v);
                    } else if (gc < 288) {
                        g_k[(size_t)px*CK + (gc-256)] = __float2half_rn(v);
                    } else {
                        g_q[(size_t)px*CK + (gc-288)] = __float2half_rn(v);
                    }
                }
            }
        }
    }
}

// ============================================================================
// Flash attention, FUSED S->P->PV in registers (no P smem, no P barrier).
// 16 warps: warp (rg = w&3: 32 q-rows) x (cg = w>>2: 64-d quarter).
// Each warp computes the FULL 64-col S strip for its rows (4x dup) and
// immediately consumes its own P frags per k16 slice. Row sums warp-local.
// j-tile 64, 3-deep K/V, 1 barrier/iter (K/V rotation only).
// ============================================================================
#define JT 64
#define NIT (NPIX/JT)
#define OFF_Q  0u
#define OFF_K  8192u
#define KBUF   4096u
#define OFF_V  20480u
#define VBUF   32768u
#define ATTN_SMEM (OFF_V + 3*VBUF)   // 118784

__device__ __forceinline__ void copy_kv(uint32_t kb, uint32_t vb,
                                        int t, int b, int j0)
{
    if (t < 256) { // K tile: 64 rows x 64B packed 2/frame
        const int j = t >> 2, c = t & 3;
        cpa16(kb + (j>>1)*128 + (j&1)*64 + c*16,
              g_k + (size_t)(b*NPIX + j0 + j)*CK + c*8);
    }
    { // V tile: 256 d-rows x 128B swizzled
        const int dd = t >> 1;
        const __nv_bfloat16* src = g_hT + (size_t)dd*TOTPIX + (b*NPIX + j0);
        #pragma unroll
        for (int i = 0; i < 4; i++) {
            int c = (t & 1)*4 + i;
            cpa16(vb + dd*128 + ((c*16) ^ ((dd&7)<<4)), src + c*8);
        }
    }
}

__global__ __launch_bounds__(512, 1) void attn_kernel(
    const float* __restrict__ x,
    const float* __restrict__ gamma_p,
    float* __restrict__ out)
{
    extern __shared__ char sm[];
    const uint32_t smb = smem_u32(sm);

    const int t = threadIdx.x;
    const int w = t >> 5;
    const int lane = t & 31;
    const int b = blockIdx.y;
    const int q0 = blockIdx.x * 128;
    const size_t rowb = (size_t)(b*NPIX + q0);

    const int rs = (w & 3) * 32;     // rowgroup
    const int dh = (w >> 2) * 64;    // d-quarter

    // prologue: group0 = {Q, K(0), V(0)}, group1 = {K(1), V(1)}
    {
        const int j = t >> 2, c = t & 3;
        cpa16(smb + OFF_Q + (j>>1)*128 + (j&1)*64 + c*16,
              g_q + (rowb + j)*CK + c*8);
    }
    copy_kv(smb + OFF_K, smb + OFF_V, t, b, 0);
    CPA_COMMIT();
    copy_kv(smb + OFF_K + KBUF, smb + OFF_V + VBUF, t, b, JT);
    CPA_COMMIT();
    CPA_WAIT(1);          // Q + K(0) + V(0) ready
    __syncthreads();

    uint32_t aq[2][2][4];
    #pragma unroll
    for (int m = 0; m < 2; m++)
        #pragma unroll
        for (int kk = 0; kk < 2; kk++)
            ldsm4(addrA_pk(smb + OFF_Q, rs + 16*m, kk*32, lane), aq[m][kk]);

    float o[2][8][4];
    #pragma unroll
    for (int m = 0; m < 2; m++)
        #pragma unroll
        for (int n = 0; n < 8; n++)
            { o[m][n][0]=0.f; o[m][n][1]=0.f; o[m][n][2]=0.f; o[m][n][3]=0.f; }
    float lr[4] = {0.f, 0.f, 0.f, 0.f};

    for (int it = 0; it < NIT; it++) {
        CPA_WAIT(0);       // K/V(it), K/V(it+1) complete
        __syncthreads();   // prev-iter reads of rotating bufs done

        if (it + 2 < NIT) {   // prefetch K/V(it+2): buffer free (3-deep)
            copy_kv(smb + OFF_K + (uint32_t)((it+2)%3)*KBUF,
                    smb + OFF_V + (uint32_t)((it+2)%3)*VBUF, t, b, (it+2)*JT);
            CPA_COMMIT();
        }

        const uint32_t kb = smb + OFF_K + (uint32_t)(it % 3)*KBUF;
        const uint32_t vb = smb + OFF_V + (uint32_t)(it % 3)*VBUF;

        // ---- per k16 slice: S(32x16) -> exp -> P frags -> PV slice ----
        #pragma unroll
        for (int j16 = 0; j16 < 4; j16++) {
            uint32_t KB0[4], KB1[4];
            ldsm4(addrB_pk(kb, j16*16, 0,  lane), KB0);
            ldsm4(addrB_pk(kb, j16*16, 32, lane), KB1);

            uint32_t P[2][4];
            #pragma unroll
            for (int m = 0; m < 2; m++) {
                float s0[4] = {0,0,0,0}, s1[4] = {0,0,0,0};
                mma_f16(s0, aq[m][0], KB0[0], KB0[1]);
                mma_f16(s1, aq[m][0], KB0[2], KB0[3]);
                mma_f16(s0, aq[m][1], KB1[0], KB1[1]);
                mma_f16(s1, aq[m][1], KB1[2], KB1[3]);

                float e00 = ex2(s0[0]-SHIFT), e01 = ex2(s0[1]-SHIFT);
                float e02 = ex2(s0[2]-SHIFT), e03 = ex2(s0[3]-SHIFT);
                float e10 = ex2(s1[0]-SHIFT), e11 = ex2(s1[1]-SHIFT);
                float e12 = ex2(s1[2]-SHIFT), e13 = ex2(s1[3]-SHIFT);
                lr[2*m]   += e00 + e01 + e10 + e11;
                lr[2*m+1] += e02 + e03 + e12 + e13;
                // C-frag -> A-frag identity (validated R7)
                P[m][0] = bf2u32(e00, e01);
                P[m][1] = bf2u32(e02, e03);
                P[m][2] = bf2u32(e10, e11);
                P[m][3] = bf2u32(e12, e13);
            }

            #pragma unroll
            for (int n16 = 0; n16 < 4; n16++) {
                uint32_t Bv[4];
                ldsm4(addrB(vb, dh + n16*16, j16*32, 128, lane), Bv);
                mma_bf16(o[0][n16*2],   P[0], Bv[0], Bv[1]);
                mma_bf16(o[0][n16*2+1], P[0], Bv[2], Bv[3]);
                mma_bf16(o[1][n16*2],   P[1], Bv[0], Bv[1]);
                mma_bf16(o[1][n16*2+1], P[1], Bv[2], Bv[3]);
            }
        }
    }

    // ---- row sums: quad shuffles (warp covers full k-range -> warp-local) ----
    #pragma unroll
    for (int i = 0; i < 4; i++) {
        lr[i] += __shfl_xor_sync(0xffffffffu, lr[i], 1);
        lr[i] += __shfl_xor_sync(0xffffffffu, lr[i], 2);
    }

    // ---- epilogue: y = gamma * O/l + x ----
    const float gamma = *gamma_p;
    #pragma unroll
    for (int m = 0; m < 2; m++) {
        const int ra = rs + 16*m + (lane >> 2);
        const int rb2 = ra + 8;
        const float ga = gamma / lr[2*m];
        const float gb = gamma / lr[2*m+1];
        #pragma unroll
        for (int n = 0; n < 8; n++) {
            const float* oo = o[m][n];
            const int d = dh + (n>>1)*16 + (n&1)*8 + (lane & 3)*2;
            const size_t ea = (rowb + ra)*CDIM + d;
            const size_t eb = (rowb + rb2)*CDIM + d;
            float2 xa = *(const float2*)(x + ea);
            float2 xb = *(const float2*)(x + eb);
            float2 ya, yb;
            ya.x = fmaf(ga, oo[0], xa.x);
            ya.y = fmaf(ga, oo[1], xa.y);
            yb.x = fmaf(gb, oo[2], xb.x);
            yb.y = fmaf(gb, oo[3], xb.y);
            *(float2*)(out + ea) = ya;
            *(float2*)(out + eb) = yb;
        }
    }
}

// ============================================================================
extern "C" void kernel_launch(void* const* d_in, const int* in_sizes, int n_in,
                              void* d_out, int out_size)
{
    const float* x     = (const float*)d_in[0];
    const float* Wf    = (const float*)d_in[1];
    const float* bf    = (const float*)d_in[2];
    const float* Wg    = (const float*)d_in[3];
    const float* bg    = (const float*)d_in[4];
    const float* Wh    = (const float*)d_in[5];
    const float* bh    = (const float*)d_in[6];
    const float* gamma = (const float*)d_in[7];
    float* out = (float*)d_out;
    (void)in_sizes; (void)n_in; (void)out_size;

    cudaFuncSetAttribute(attn_kernel,
                         cudaFuncAttributeMaxDynamicSharedMemorySize, ATTN_SMEM);
    cudaFuncSetAttribute(proj_kernel,
                         cudaFuncAttributeMaxDynamicSharedMemorySize, PJ_SMEM);

    wsplit_kernel<<<320, 256>>>(Wf, Wg, Wh);
    xsplit_kernel<<<TOTPIX*CDIM/8/256, 256>>>(x);
    proj_kernel<<<dim3(TOTPIX/128, 5), 256, PJ_SMEM>>>(bf, bg, bh);
    attn_kernel<<<dim3(NPIX/128, NB), 512, ATTN_SMEM>>>(x, gamma, out);
}

// round 15
// speedup vs baseline: 1.2138x; 1.2138x over previous
#include <cuda_runtime.h>
#include <cuda_bf16.h>
#include <cuda_fp16.h>
#include <cstdint>

#define NB 4
#define NPIX 4096
#define CDIM 256
#define CK 32
#define TOTPIX (NB*NPIX)
#define LOG2E 1.4426950408889634f
#define SHIFT 28.853900817779268f   // 20 * log2(e)

__device__ __half g_k[TOTPIX*CK];                   // keys fp16
__device__ __half g_q[TOTPIX*CK];                   // queries fp16, pre-scaled log2e
__device__ __nv_bfloat16 g_hT[(size_t)CDIM*TOTPIX]; // values bf16, channel-major
__device__ __half g_xh[(size_t)TOTPIX*CDIM];        // x as fp16 [px][256]
__device__ __half g_wT[320*CDIM];                   // [col][256] fp16 (Wg pre-scaled)

__device__ __forceinline__ uint32_t bf2u32(float a, float b) {
    __nv_bfloat162 h = __floats2bfloat162_rn(a, b);
    return *reinterpret_cast<uint32_t*>(&h);
}
__device__ __forceinline__ uint32_t smem_u32(const void* p) {
    uint32_t r;
    asm("{ .reg .u64 t; cvta.to.shared.u64 t, %1; cvt.u32.u64 %0, t; }" : "=r"(r) : "l"(p));
    return r;
}
__device__ __forceinline__ float ex2(float x) {
    float y; asm("ex2.approx.f32 %0,%1;" : "=f"(y) : "f"(x)); return y;
}
__device__ __forceinline__ void mma_bf16(float* c, const uint32_t* a, uint32_t b0, uint32_t b1) {
    asm volatile(
        "mma.sync.aligned.m16n8k16.row.col.f32.bf16.bf16.f32 "
        "{%0,%1,%2,%3},{%4,%5,%6,%7},{%8,%9},{%0,%1,%2,%3};"
        : "+f"(c[0]), "+f"(c[1]), "+f"(c[2]), "+f"(c[3])
        : "r"(a[0]), "r"(a[1]), "r"(a[2]), "r"(a[3]), "r"(b0), "r"(b1));
}
__device__ __forceinline__ void mma_f16(float* c, const uint32_t* a, uint32_t b0, uint32_t b1) {
    asm volatile(
        "mma.sync.aligned.m16n8k16.row.col.f32.f16.f16.f32 "
        "{%0,%1,%2,%3},{%4,%5,%6,%7},{%8,%9},{%0,%1,%2,%3};"
        : "+f"(c[0]), "+f"(c[1]), "+f"(c[2]), "+f"(c[3])
        : "r"(a[0]), "r"(a[1]), "r"(a[2]), "r"(a[3]), "r"(b0), "r"(b1));
}
__device__ __forceinline__ void ldsm4(uint32_t addr, uint32_t* r) {
    asm volatile("ldmatrix.sync.aligned.m8n8.x4.shared.b16 {%0,%1,%2,%3},[%4];"
        : "=r"(r[0]), "=r"(r[1]), "=r"(r[2]), "=r"(r[3]) : "r"(addr));
}
__device__ __forceinline__ void stsm4(uint32_t addr, uint32_t r0, uint32_t r1,
                                      uint32_t r2, uint32_t r3) {
    asm volatile("stmatrix.sync.aligned.m8n8.x4.shared.b16 [%0], {%1,%2,%3,%4};"
        :: "r"(addr), "r"(r0), "r"(r1), "r"(r2), "r"(r3) : "memory");
}
__device__ __forceinline__ void cpa16(uint32_t dst, const void* src) {
    asm volatile("cp.async.cg.shared.global [%0],[%1],16;" :: "r"(dst), "l"(src) : "memory");
}
#define CPA_COMMIT() asm volatile("cp.async.commit_group;" ::: "memory")
#define CPA_WAIT(n)  asm volatile("cp.async.wait_group %0;" :: "n"(n) : "memory")

// swizzled layouts (stride = row bytes; swizzle bits [4:6] by row&7)
__device__ __forceinline__ uint32_t addrA(uint32_t base, int rbase, int kb, int stride, int lane) {
    int g = lane >> 3, lr = lane & 7;
    int r = rbase + lr + (g & 1) * 8;
    int kk = kb + (g & 2) * 8;
    return base + r * stride + (kk ^ ((r & 7) << 4));
}
__device__ __forceinline__ uint32_t addrB(uint32_t base, int rbase, int kb, int stride, int lane) {
    int g = lane >> 3, lr = lane & 7;
    int r = rbase + lr + (g & 2) * 4;
    int kk = kb + (g & 1) * 16;
    return base + r * stride + (kk ^ ((r & 7) << 4));
}
// packed 64B-rows (2 rows per 128B frame) layouts (Q, K) -- conflict-free
__device__ __forceinline__ uint32_t addrA_pk(uint32_t base, int rbase, int kb, int lane) {
    int g = lane >> 3, lr = lane & 7;
    int r = rbase + lr + (g & 1) * 8;
    int kk = kb + (g & 2) * 8;
    return base + (r >> 1)*128 + (r & 1)*64 + kk;
}
__device__ __forceinline__ uint32_t addrB_pk(uint32_t base, int rbase, int kb, int lane) {
    int g = lane >> 3, lr = lane & 7;
    int r = rbase + lr + (g & 2) * 4;
    int kk = kb + (g & 1) * 16;
    return base + (r >> 1)*128 + (r & 1)*64 + kk;
}

// ============================================================================
// Pre-kernel (fused): x f32 -> fp16 AND weight transpose -> g_wT (blocks<320)
// ============================================================================
__global__ __launch_bounds__(256) void prep_kernel(
    const float* __restrict__ x,
    const float* __restrict__ Wf, const float* __restrict__ Wg,
    const float* __restrict__ Wh)
{
    const size_t gid = (size_t)blockIdx.x * 256 + threadIdx.x;
    const float4 v0 = *(const float4*)(x + gid*8);
    const float4 v1 = *(const float4*)(x + gid*8 + 4);
    __half2 h[4];
    h[0] = __floats2half2_rn(v0.x, v0.y);
    h[1] = __floats2half2_rn(v0.z, v0.w);
    h[2] = __floats2half2_rn(v1.x, v1.y);
    h[3] = __floats2half2_rn(v1.z, v1.w);
    *(uint4*)(g_xh + gid*8) = *(const uint4*)h;

    if (blockIdx.x < 320) {
        const int col = blockIdx.x;
        const int k = threadIdx.x;
        float w;
        if (col < 256)      w = Wh[k*256 + col];
        else if (col < 288) w = Wf[k*32 + (col-256)];
        else                w = Wg[k*32 + (col-288)] * LOG2E;
        g_wT[col*CDIM + k] = __float2half_rn(w);
    }
}

// ============================================================================
// Projection GEMM: C[16384,320] = x_f16 @ g_wT^T, K=256 in 2 chunks.
// ============================================================================
#define PJ_AB   32768u
#define PJ_BB   16384u
#define PJ_SMEM (2*PJ_AB + 2*PJ_BB)

__device__ __forceinline__ void pj_copy(uint32_t smb, int t, int rows0, int c0, int n)
{
    const uint32_t ab = smb + (uint32_t)(n & 1)*PJ_AB;
    const uint32_t bb = smb + 2*PJ_AB + (uint32_t)(n & 1)*PJ_BB;
    {
        const int r = t >> 1, half = t & 1;
        const __half* src = g_xh + (size_t)(rows0 + r)*CDIM + n*128;
        #pragma unroll
        for (int i = 0; i < 8; i++) {
            int p = half*8 + i;
            cpa16(ab + r*256 + ((p*16) ^ ((r & 7) << 4)), src + p*8);
        }
    }
    {
        const int c = t >> 2, q = t & 3;
        const __half* src = g_wT + (size_t)(c0 + c)*CDIM + n*128;
        #pragma unroll
        for (int i = 0; i < 4; i++) {
            int p = q*4 + i;
            cpa16(bb + c*256 + ((p*16) ^ ((c & 7) << 4)), src + p*8);
        }
    }
}

__global__ __launch_bounds__(256, 2) void proj_kernel(
    const float* __restrict__ bfp, const float* __restrict__ bgp,
    const float* __restrict__ bhp)
{
    extern __shared__ char sm[];
    const uint32_t smb = smem_u32(sm);
    const int t = threadIdx.x;
    const int w = t >> 5;
    const int lane = t & 31;
    const int rows0 = blockIdx.x * 128;
    const int c0 = blockIdx.y * 64;
    const int rs = (w & 3) * 32;
    const int cs = (w >> 2) * 32;

    float acc[2][4][4];
    #pragma unroll
    for (int m = 0; m < 2; m++)
        #pragma unroll
        for (int n = 0; n < 4; n++)
            { acc[m][n][0]=0.f; acc[m][n][1]=0.f; acc[m][n][2]=0.f; acc[m][n][3]=0.f; }

    pj_copy(smb, t, rows0, c0, 0);
    CPA_COMMIT();
    pj_copy(smb, t, rows0, c0, 1);
    CPA_COMMIT();
    CPA_WAIT(1);
    __syncthreads();

    #pragma unroll
    for (int n = 0; n < 2; n++) {
        if (n == 1) { CPA_WAIT(0); __syncthreads(); }
        const uint32_t ab = smb + (uint32_t)(n & 1)*PJ_AB;
        const uint32_t bb = smb + 2*PJ_AB + (uint32_t)(n & 1)*PJ_BB;
        #pragma unroll
        for (int k16 = 0; k16 < 8; k16++) {
            uint32_t a0[4], a1[4];
            ldsm4(addrA(ab, rs,      k16*32, 256, lane), a0);
            ldsm4(addrA(ab, rs + 16, k16*32, 256, lane), a1);
            #pragma unroll
            for (int n16 = 0; n16 < 2; n16++) {
                uint32_t B[4];
                ldsm4(addrB(bb, cs + n16*16, k16*32, 256, lane), B);
                mma_f16(acc[0][n16*2],   a0, B[0], B[1]);
                mma_f16(acc[0][n16*2+1], a0, B[2], B[3]);
                mma_f16(acc[1][n16*2],   a1, B[0], B[1]);
                mma_f16(acc[1][n16*2+1], a1, B[2], B[3]);
            }
        }
    }

    #pragma unroll
    for (int n = 0; n < 4; n++) {
        const int cA = cs + n*8 + (lane & 3)*2;
        #pragma unroll
        for (int half = 0; half < 2; half++) {
            const int gc = c0 + cA + half;
            float bias;
            if (gc < 256)      bias = bhp[gc];
            else if (gc < 288) bias = bfp[gc-256];
            else               bias = bgp[gc-288] * LOG2E;
            #pragma unroll
            for (int m = 0; m < 2; m++) {
                #pragma unroll
                for (int eh = 0; eh < 2; eh++) {
                    const int r = rs + m*16 + (lane >> 2) + eh*8;
                    const int px = rows0 + r;
                    float v = acc[m][n][eh*2 + half] + bias;
                    if (gc < 256) {
                        g_hT[(size_t)gc*TOTPIX + px] = __float2bfloat16_rn(v);
                    } else if (gc < 288) {
                        g_k[(size_t)px*CK + (gc-256)] = __float2half_rn(v);
                    } else {
                        g_q[(size_t)px*CK + (gc-288)] = __float2half_rn(v);
                    }
                }
            }
        }
    }
}

// ============================================================================
// Flash attention (R12 structure): 16 warps, software-pipelined, PV-first
// with hoisted K-fragment loads. j-tile 64, 3-deep K/V, double P, 1 bar/iter.
//   warp (rg = w&3: 32 q-rows) x (cg = w>>2: 16 S-cols / 64-d quarter)
// ============================================================================
#define JT 64
#define NIT (NPIX/JT)
#define OFF_LS 0u
#define OFF_Q  512u
#define OFF_P  8704u
#define PBUF   16384u
#define OFF_K  41472u
#define KBUF   4096u
#define OFF_V  53760u
#define VBUF   32768u
#define ATTN_SMEM (OFF_V + 3*VBUF)   // 152064

__device__ __forceinline__ void copy_kv(uint32_t kb, uint32_t vb,
                                        int t, int b, int j0)
{
    if (t < 256) { // K tile: 64 rows x 64B packed 2/frame
        const int j = t >> 2, c = t & 3;
        cpa16(kb + (j>>1)*128 + (j&1)*64 + c*16,
              g_k + (size_t)(b*NPIX + j0 + j)*CK + c*8);
    }
    { // V tile: 256 d-rows x 128B swizzled
        const int dd = t >> 1;
        const __nv_bfloat16* src = g_hT + (size_t)dd*TOTPIX + (b*NPIX + j0);
        #pragma unroll
        for (int i = 0; i < 4; i++) {
            int c = (t & 1)*4 + i;
            cpa16(vb + dd*128 + ((c*16) ^ ((dd&7)<<4)), src + c*8);
        }
    }
}

// S body from preloaded K-frags -> exp -> stsm into pb; accumulates lr
__device__ __forceinline__ void s_body(const uint32_t KB[2][4], uint32_t pb,
                                       const uint32_t aq[2][2][4],
                                       int rs, int cg, int lane, float* lr)
{
    #pragma unroll
    for (int m = 0; m < 2; m++) {
        float s[2][4];
        #pragma unroll
        for (int nn = 0; nn < 2; nn++)
            { s[nn][0]=0.f; s[nn][1]=0.f; s[nn][2]=0.f; s[nn][3]=0.f; }
        #pragma unroll
        for (int k16 = 0; k16 < 2; k16++) {
            mma_f16(s[0], aq[m][k16], KB[k16][0], KB[k16][1]);
            mma_f16(s[1], aq[m][k16], KB[k16][2], KB[k16][3]);
        }
        uint32_t P01[2], P23[2];
        #pragma unroll
        for (int nn = 0; nn < 2; nn++) {
            float e0 = ex2(s[nn][0]-SHIFT), e1 = ex2(s[nn][1]-SHIFT);
            float e2 = ex2(s[nn][2]-SHIFT), e3 = ex2(s[nn][3]-SHIFT);
            lr[2*m]   += e0 + e1;
            lr[2*m+1] += e2 + e3;
            P01[nn] = bf2u32(e0, e1);
            P23[nn] = bf2u32(e2, e3);
        }
        stsm4(addrA(pb, rs + 16*m, cg*32, 128, lane),
              P01[0], P23[0], P01[1], P23[1]);
    }
}

// PV(it): rows rs..rs+31 x d-quarter dh, k = JT
__device__ __forceinline__ void pv_phase(uint32_t pb, uint32_t vb,
                                         int rs, int dh, int lane,
                                         float o[2][8][4])
{
    #pragma unroll
    for (int j16 = 0; j16 < 4; j16++) {
        uint32_t A0[4], A1[4];
        ldsm4(addrA(pb, rs,      j16*32, 128, lane), A0);
        ldsm4(addrA(pb, rs + 16, j16*32, 128, lane), A1);
        #pragma unroll
        for (int n16 = 0; n16 < 4; n16++) {
            uint32_t Bv[4];
            ldsm4(addrB(vb, dh + n16*16, j16*32, 128, lane), Bv);
            mma_bf16(o[0][n16*2],   A0, Bv[0], Bv[1]);
            mma_bf16(o[0][n16*2+1], A0, Bv[2], Bv[3]);
            mma_bf16(o[1][n16*2],   A1, Bv[0], Bv[1]);
            mma_bf16(o[1][n16*2+1], A1, Bv[2], Bv[3]);
        }
    }
}

__global__ __launch_bounds__(512, 1) void attn_kernel(
    const float* __restrict__ x,
    const float* __restrict__ gamma_p,
    float* __restrict__ out)
{
    extern __shared__ char sm[];
    const uint32_t smb = smem_u32(sm);
    float* ls = (float*)(sm + OFF_LS);

    const int t = threadIdx.x;
    const int w = t >> 5;
    const int lane = t & 31;
    const int b = blockIdx.y;
    const int q0 = blockIdx.x * 128;
    const size_t rowb = (size_t)(b*NPIX + q0);

    const int rs = (w & 3) * 32;     // rowgroup
    const int cg = w >> 2;           // colgroup (S 16-col slice / PV 64-d quarter)
    const int dh = cg * 64;

    if (t < 128) ls[t] = 0.f;

    // prologue: group0 = {Q, K(0), V(0)}, group1 = {K(1), V(1)}
    {
        const int j = t >> 2, c = t & 3;
        cpa16(smb + OFF_Q + (j>>1)*128 + (j&1)*64 + c*16,
              g_q + (rowb + j)*CK + c*8);
    }
    copy_kv(smb + OFF_K, smb + OFF_V, t, b, 0);
    CPA_COMMIT();
    copy_kv(smb + OFF_K + KBUF, smb + OFF_V + VBUF, t, b, JT);
    CPA_COMMIT();
    CPA_WAIT(1);          // Q + K(0) + V(0) ready
    __syncthreads();

    uint32_t aq[2][2][4];
    #pragma unroll
    for (int m = 0; m < 2; m++)
        #pragma unroll
        for (int kk = 0; kk < 2; kk++)
            ldsm4(addrA_pk(smb + OFF_Q, rs + 16*m, kk*32, lane), aq[m][kk]);

    float o[2][8][4];
    #pragma unroll
    for (int m = 0; m < 2; m++)
        #pragma unroll
        for (int n = 0; n < 8; n++)
            { o[m][n][0]=0.f; o[m][n][1]=0.f; o[m][n][2]=0.f; o[m][n][3]=0.f; }
    float lr[4] = {0.f, 0.f, 0.f, 0.f};

    // S(0) -> P[0]
    {
        uint32_t KB[2][4];
        ldsm4(addrB_pk(smb + OFF_K, cg*16, 0,  lane), KB[0]);
        ldsm4(addrB_pk(smb + OFF_K, cg*16, 32, lane), KB[1]);
        s_body(KB, smb + OFF_P, aq, rs, cg, lane, lr);
    }

    for (int it = 0; it < NIT; it++) {
        CPA_WAIT(0);       // K/V(it+1) complete
        __syncthreads();   // PV(it-1)/S(it) reads done; copies + P(it) visible

        if (it + 2 < NIT) {   // prefetch K/V(it+2): buffers free (3-deep)
            copy_kv(smb + OFF_K + (uint32_t)((it+2)%3)*KBUF,
                    smb + OFF_V + (uint32_t)((it+2)%3)*VBUF, t, b, (it+2)*JT);
            CPA_COMMIT();
        }

        // ---- hoisted K-frag loads for S(it+1) (latency hidden by PV) ----
        uint32_t KB[2][4];
        const bool more = (it + 1 < NIT);
        if (more) {
            const uint32_t kb = smb + OFF_K + (uint32_t)((it+1) % 3)*KBUF;
            ldsm4(addrB_pk(kb, cg*16, 0,  lane), KB[0]);
            ldsm4(addrB_pk(kb, cg*16, 32, lane), KB[1]);
        }

        // ---- PV(it) first: tensor-heavy stream right after the barrier ----
        const uint32_t pb = smb + OFF_P + (uint32_t)(it & 1)*PBUF;
        const uint32_t vb = smb + OFF_V + (uint32_t)(it % 3)*VBUF;
        pv_phase(pb, vb, rs, dh, lane, o);

        // ---- S(it+1) -> P[(it+1)&1] ----
        if (more)
            s_body(KB, smb + OFF_P + (uint32_t)((it+1) & 1)*PBUF,
                   aq, rs, cg, lane, lr);
    }

    // ---- row sums: quad shuffles then cross-colgroup smem atomics ----
    #pragma unroll
    for (int i = 0; i < 4; i++) {
        lr[i] += __shfl_xor_sync(0xffffffffu, lr[i], 1);
        lr[i] += __shfl_xor_sync(0xffffffffu, lr[i], 2);
    }
    if ((lane & 3) == 0) {
        const int r = rs + (lane >> 2);
        atomicAdd(&ls[r],      lr[0]);
        atomicAdd(&ls[r + 8],  lr[1]);
        atomicAdd(&ls[r + 16], lr[2]);
        atomicAdd(&ls[r + 24], lr[3]);
    }
    __syncthreads();

    // ---- epilogue: y = gamma * O/l + x ----
    const float gamma = *gamma_p;
    #pragma unroll
    for (int m = 0; m < 2; m++) {
        const int ra = rs + 16*m + (lane >> 2);
        const int rb2 = ra + 8;
        const float ga = gamma / ls[ra];
        const float gb = gamma / ls[rb2];
        #pragma unroll
        for (int n = 0; n < 8; n++) {
            const float* oo = o[m][n];
            const int d = dh + (n>>1)*16 + (n&1)*8 + (lane & 3)*2;
            const size_t ea = (rowb + ra)*CDIM + d;
            const size_t eb = (rowb + rb2)*CDIM + d;
            float2 xa = *(const float2*)(x + ea);
            float2 xb = *(const float2*)(x + eb);
            float2 ya, yb;
            ya.x = fmaf(ga, oo[0], xa.x);
            ya.y = fmaf(ga, oo[1], xa.y);
            yb.x = fmaf(gb, oo[2], xb.x);
            yb.y = fmaf(gb, oo[3], xb.y);
            *(float2*)(out + ea) = ya;
            *(float2*)(out + eb) = yb;
        }
    }
}

// ============================================================================
extern "C" void kernel_launch(void* const* d_in, const int* in_sizes, int n_in,
                              void* d_out, int out_size)
{
    const float* x     = (const float*)d_in[0];
    const float* Wf    = (const float*)d_in[1];
    const float* bf    = (const float*)d_in[2];
    const float* Wg    = (const float*)d_in[3];
    const float* bg    = (const float*)d_in[4];
    const float* Wh    = (const float*)d_in[5];
    const float* bh    = (const float*)d_in[6];
    const float* gamma = (const float*)d_in[7];
    float* out = (float*)d_out;
    (void)in_sizes; (void)n_in; (void)out_size;

    cudaFuncSetAttribute(attn_kernel,
                         cudaFuncAttributeMaxDynamicSharedMemorySize, ATTN_SMEM);
    cudaFuncSetAttribute(proj_kernel,
                         cudaFuncAttributeMaxDynamicSharedMemorySize, PJ_SMEM);

    prep_kernel<<<TOTPIX*CDIM/8/256, 256>>>(x, Wf, Wg, Wh);
    proj_kernel<<<dim3(TOTPIX/128, 5), 256, PJ_SMEM>>>(bf, bg, bh);
    attn_kernel<<<dim3(NPIX/128, NB), 512, ATTN_SMEM>>>(x, gamma, out);
}

// round 16
// speedup vs baseline: 1.3110x; 1.0801x over previous
#include <cuda_runtime.h>
#include <cuda_bf16.h>
#include <cuda_fp16.h>
#include <cstdint>

#define NB 4
#define NPIX 4096
#define CDIM 256
#define CK 32
#define TOTPIX (NB*NPIX)
#define LOG2E 1.4426950408889634f
#define SHIFT 28.853900817779268f   // 20 * log2(e)

__device__ __half g_k[TOTPIX*CK];                   // keys fp16
__device__ __half g_q[TOTPIX*CK];                   // queries fp16, pre-scaled log2e
__device__ __nv_bfloat16 g_hT[(size_t)CDIM*TOTPIX]; // values bf16, channel-major
__device__ __half g_xh[(size_t)TOTPIX*CDIM];        // x as fp16 [px][256]
__device__ __half g_wT[320*CDIM];                   // [col][256] fp16 (Wg pre-scaled)

__device__ __forceinline__ uint32_t bf2u32(float a, float b) {
    __nv_bfloat162 h = __floats2bfloat162_rn(a, b);
    return *reinterpret_cast<uint32_t*>(&h);
}
__device__ __forceinline__ uint32_t smem_u32(const void* p) {
    uint32_t r;
    asm("{ .reg .u64 t; cvta.to.shared.u64 t, %1; cvt.u32.u64 %0, t; }" : "=r"(r) : "l"(p));
    return r;
}
__device__ __forceinline__ float ex2(float x) {
    float y; asm("ex2.approx.f32 %0,%1;" : "=f"(y) : "f"(x)); return y;
}
__device__ __forceinline__ void mma_bf16(float* c, const uint32_t* a, uint32_t b0, uint32_t b1) {
    asm volatile(
        "mma.sync.aligned.m16n8k16.row.col.f32.bf16.bf16.f32 "
        "{%0,%1,%2,%3},{%4,%5,%6,%7},{%8,%9},{%0,%1,%2,%3};"
        : "+f"(c[0]), "+f"(c[1]), "+f"(c[2]), "+f"(c[3])
        : "r"(a[0]), "r"(a[1]), "r"(a[2]), "r"(a[3]), "r"(b0), "r"(b1));
}
__device__ __forceinline__ void mma_f16(float* c, const uint32_t* a, uint32_t b0, uint32_t b1) {
    asm volatile(
        "mma.sync.aligned.m16n8k16.row.col.f32.f16.f16.f32 "
        "{%0,%1,%2,%3},{%4,%5,%6,%7},{%8,%9},{%0,%1,%2,%3};"
        : "+f"(c[0]), "+f"(c[1]), "+f"(c[2]), "+f"(c[3])
        : "r"(a[0]), "r"(a[1]), "r"(a[2]), "r"(a[3]), "r"(b0), "r"(b1));
}
__device__ __forceinline__ void ldsm4(uint32_t addr, uint32_t* r) {
    asm volatile("ldmatrix.sync.aligned.m8n8.x4.shared.b16 {%0,%1,%2,%3},[%4];"
        : "=r"(r[0]), "=r"(r[1]), "=r"(r[2]), "=r"(r[3]) : "r"(addr));
}
__device__ __forceinline__ void stsm4(uint32_t addr, uint32_t r0, uint32_t r1,
                                      uint32_t r2, uint32_t r3) {
    asm volatile("stmatrix.sync.aligned.m8n8.x4.shared.b16 [%0], {%1,%2,%3,%4};"
        :: "r"(addr), "r"(r0), "r"(r1), "r"(r2), "r"(r3) : "memory");
}
__device__ __forceinline__ void cpa16(uint32_t dst, const void* src) {
    asm volatile("cp.async.cg.shared.global [%0],[%1],16;" :: "r"(dst), "l"(src) : "memory");
}
#define CPA_COMMIT() asm volatile("cp.async.commit_group;" ::: "memory")
#define CPA_WAIT(n)  asm volatile("cp.async.wait_group %0;" :: "n"(n) : "memory")

// swizzled layouts (stride = row bytes; swizzle bits [4:6] by row&7)
__device__ __forceinline__ uint32_t addrA(uint32_t base, int rbase, int kb, int stride, int lane) {
    int g = lane >> 3, lr = lane & 7;
    int r = rbase + lr + (g & 1) * 8;
    int kk = kb + (g & 2) * 8;
    return base + r * stride + (kk ^ ((r & 7) << 4));
}
__device__ __forceinline__ uint32_t addrB(uint32_t base, int rbase, int kb, int stride, int lane) {
    int g = lane >> 3, lr = lane & 7;
    int r = rbase + lr + (g & 2) * 4;
    int kk = kb + (g & 1) * 16;
    return base + r * stride + (kk ^ ((r & 7) << 4));
}
// packed 64B-rows (2 rows per 128B frame) layouts (Q, K) -- conflict-free
__device__ __forceinline__ uint32_t addrA_pk(uint32_t base, int rbase, int kb, int lane) {
    int g = lane >> 3, lr = lane & 7;
    int r = rbase + lr + (g & 1) * 8;
    int kk = kb + (g & 2) * 8;
    return base + (r >> 1)*128 + (r & 1)*64 + kk;
}
__device__ __forceinline__ uint32_t addrB_pk(uint32_t base, int rbase, int kb, int lane) {
    int g = lane >> 3, lr = lane & 7;
    int r = rbase + lr + (g & 2) * 4;
    int kk = kb + (g & 1) * 16;
    return base + (r >> 1)*128 + (r & 1)*64 + kk;
}

// ============================================================================
// Pre-kernel (fused): x f32 -> fp16 AND weight transpose -> g_wT (blocks<320)
// ============================================================================
__global__ __launch_bounds__(256) void prep_kernel(
    const float* __restrict__ x,
    const float* __restrict__ Wf, const float* __restrict__ Wg,
    const float* __restrict__ Wh)
{
    const size_t gid = (size_t)blockIdx.x * 256 + threadIdx.x;
    const float4 v0 = *(const float4*)(x + gid*8);
    const float4 v1 = *(const float4*)(x + gid*8 + 4);
    __half2 h[4];
    h[0] = __floats2half2_rn(v0.x, v0.y);
    h[1] = __floats2half2_rn(v0.z, v0.w);
    h[2] = __floats2half2_rn(v1.x, v1.y);
    h[3] = __floats2half2_rn(v1.z, v1.w);
    *(uint4*)(g_xh + gid*8) = *(const uint4*)h;

    if (blockIdx.x < 320) {
        const int col = blockIdx.x;
        const int k = threadIdx.x;
        float w;
        if (col < 256)      w = Wh[k*256 + col];
        else if (col < 288) w = Wf[k*32 + (col-256)];
        else                w = Wg[k*32 + (col-288)] * LOG2E;
        g_wT[col*CDIM + k] = __float2half_rn(w);
    }
}

// ============================================================================
// Projection GEMM: C[16384,320] = x_f16 @ g_wT^T, K=256 in 2 chunks.
// ============================================================================
#define PJ_AB   32768u
#define PJ_BB   16384u
#define PJ_SMEM (2*PJ_AB + 2*PJ_BB)

__device__ __forceinline__ void pj_copy(uint32_t smb, int t, int rows0, int c0, int n)
{
    const uint32_t ab = smb + (uint32_t)(n & 1)*PJ_AB;
    const uint32_t bb = smb + 2*PJ_AB + (uint32_t)(n & 1)*PJ_BB;
    {
        const int r = t >> 1, half = t & 1;
        const __half* src = g_xh + (size_t)(rows0 + r)*CDIM + n*128;
        #pragma unroll
        for (int i = 0; i < 8; i++) {
            int p = half*8 + i;
            cpa16(ab + r*256 + ((p*16) ^ ((r & 7) << 4)), src + p*8);
        }
    }
    {
        const int c = t >> 2, q = t & 3;
        const __half* src = g_wT + (size_t)(c0 + c)*CDIM + n*128;
        #pragma unroll
        for (int i = 0; i < 4; i++) {
            int p = q*4 + i;
            cpa16(bb + c*256 + ((p*16) ^ ((c & 7) << 4)), src + p*8);
        }
    }
}

__global__ __launch_bounds__(256, 2) void proj_kernel(
    const float* __restrict__ bfp, const float* __restrict__ bgp,
    const float* __restrict__ bhp)
{
    extern __shared__ char sm[];
    const uint32_t smb = smem_u32(sm);
    const int t = threadIdx.x;
    const int w = t >> 5;
    const int lane = t & 31;
    const int rows0 = blockIdx.x * 128;
    const int c0 = blockIdx.y * 64;
    const int rs = (w & 3) * 32;
    const int cs = (w >> 2) * 32;

    float acc[2][4][4];
    #pragma unroll
    for (int m = 0; m < 2; m++)
        #pragma unroll
        for (int n = 0; n < 4; n++)
            { acc[m][n][0]=0.f; acc[m][n][1]=0.f; acc[m][n][2]=0.f; acc[m][n][3]=0.f; }

    pj_copy(smb, t, rows0, c0, 0);
    CPA_COMMIT();
    pj_copy(smb, t, rows0, c0, 1);
    CPA_COMMIT();
    CPA_WAIT(1);
    __syncthreads();

    #pragma unroll
    for (int n = 0; n < 2; n++) {
        if (n == 1) { CPA_WAIT(0); __syncthreads(); }
        const uint32_t ab = smb + (uint32_t)(n & 1)*PJ_AB;
        const uint32_t bb = smb + 2*PJ_AB + (uint32_t)(n & 1)*PJ_BB;
        #pragma unroll
        for (int k16 = 0; k16 < 8; k16++) {
            uint32_t a0[4], a1[4];
            ldsm4(addrA(ab, rs,      k16*32, 256, lane), a0);
            ldsm4(addrA(ab, rs + 16, k16*32, 256, lane), a1);
            #pragma unroll
            for (int n16 = 0; n16 < 2; n16++) {
                uint32_t B[4];
                ldsm4(addrB(bb, cs + n16*16, k16*32, 256, lane), B);
                mma_f16(acc[0][n16*2],   a0, B[0], B[1]);
                mma_f16(acc[0][n16*2+1], a0, B[2], B[3]);
                mma_f16(acc[1][n16*2],   a1, B[0], B[1]);
                mma_f16(acc[1][n16*2+1], a1, B[2], B[3]);
            }
        }
    }

    #pragma unroll
    for (int n = 0; n < 4; n++) {
        const int cA = cs + n*8 + (lane & 3)*2;
        #pragma unroll
        for (int half = 0; half < 2; half++) {
            const int gc = c0 + cA + half;
            float bias;
            if (gc < 256)      bias = bhp[gc];
            else if (gc < 288) bias = bfp[gc-256];
            else               bias = bgp[gc-288] * LOG2E;
            #pragma unroll
            for (int m = 0; m < 2; m++) {
                #pragma unroll
                for (int eh = 0; eh < 2; eh++) {
                    const int r = rs + m*16 + (lane >> 2) + eh*8;
                    const int px = rows0 + r;
                    float v = acc[m][n][eh*2 + half] + bias;
                    if (gc < 256) {
                        g_hT[(size_t)gc*TOTPIX + px] = __float2bfloat16_rn(v);
                    } else if (gc < 288) {
                        g_k[(size_t)px*CK + (gc-256)] = __float2half_rn(v);
                    } else {
                        g_q[(size_t)px*CK + (gc-288)] = __float2half_rn(v);
                    }
                }
            }
        }
    }
}

// ============================================================================
// Flash attention (exact R12 structure -- best known): 16 warps,
// software-pipelined (S(it+1) then PV(it)), j-tile 64, 3-deep K/V,
// double P, ONE barrier per iter.
//   warp (rg = w&3: 32 q-rows) x (cg = w>>2: 16 S-cols / 64-d quarter)
// ============================================================================
#define JT 64
#define NIT (NPIX/JT)
#define OFF_LS 0u
#define OFF_Q  512u
#define OFF_P  8704u
#define PBUF   16384u
#define OFF_K  41472u
#define KBUF   4096u
#define OFF_V  53760u
#define VBUF   32768u
#define ATTN_SMEM (OFF_V + 3*VBUF)   // 152064

__device__ __forceinline__ void copy_kv(uint32_t kb, uint32_t vb,
                                        int t, int b, int j0)
{
    if (t < 256) { // K tile: 64 rows x 64B packed 2/frame
        const int j = t >> 2, c = t & 3;
        cpa16(kb + (j>>1)*128 + (j&1)*64 + c*16,
              g_k + (size_t)(b*NPIX + j0 + j)*CK + c*8);
    }
    { // V tile: 256 d-rows x 128B swizzled
        const int dd = t >> 1;
        const __nv_bfloat16* src = g_hT + (size_t)dd*TOTPIX + (b*NPIX + j0);
        #pragma unroll
        for (int i = 0; i < 4; i++) {
            int c = (t & 1)*4 + i;
            cpa16(vb + dd*128 + ((c*16) ^ ((dd&7)<<4)), src + c*8);
        }
    }
}

// S(n) -> exp -> stsm into P[n&1]; accumulates lr
__device__ __forceinline__ void s_phase(uint32_t smb, int n,
                                        const uint32_t aq[2][2][4],
                                        int rs, int cg, int lane, float* lr)
{
    const uint32_t kb = smb + OFF_K + (uint32_t)(n % 3)*KBUF;
    const uint32_t pb = smb + OFF_P + (uint32_t)(n & 1)*PBUF;
    uint32_t KB[2][4];
    #pragma unroll
    for (int k16 = 0; k16 < 2; k16++)
        ldsm4(addrB_pk(kb, cg*16, k16*32, lane), KB[k16]);
    #pragma unroll
    for (int m = 0; m < 2; m++) {
        float s[2][4];
        #pragma unroll
        for (int nn = 0; nn < 2; nn++)
            { s[nn][0]=0.f; s[nn][1]=0.f; s[nn][2]=0.f; s[nn][3]=0.f; }
        #pragma unroll
        for (int k16 = 0; k16 < 2; k16++) {
            mma_f16(s[0], aq[m][k16], KB[k16][0], KB[k16][1]);
            mma_f16(s[1], aq[m][k16], KB[k16][2], KB[k16][3]);
        }
        uint32_t P01[2], P23[2];
        #pragma unroll
        for (int nn = 0; nn < 2; nn++) {
            float e0 = ex2(s[nn][0]-SHIFT), e1 = ex2(s[nn][1]-SHIFT);
            float e2 = ex2(s[nn][2]-SHIFT), e3 = ex2(s[nn][3]-SHIFT);
            lr[2*m]   += e0 + e1;
            lr[2*m+1] += e2 + e3;
            P01[nn] = bf2u32(e0, e1);
            P23[nn] = bf2u32(e2, e3);
        }
        stsm4(addrA(pb, rs + 16*m, cg*32, 128, lane),
              P01[0], P23[0], P01[1], P23[1]);
    }
}

__global__ __launch_bounds__(512, 1) void attn_kernel(
    const float* __restrict__ x,
    const float* __restrict__ gamma_p,
    float* __restrict__ out)
{
    extern __shared__ char sm[];
    const uint32_t smb = smem_u32(sm);
    float* ls = (float*)(sm + OFF_LS);

    const int t = threadIdx.x;
    const int w = t >> 5;
    const int lane = t & 31;
    const int b = blockIdx.y;
    const int q0 = blockIdx.x * 128;
    const size_t rowb = (size_t)(b*NPIX + q0);

    const int rs = (w & 3) * 32;     // rowgroup
    const int cg = w >> 2;           // colgroup (S 16-col slice / PV 64-d quarter)
    const int dh = cg * 64;

    if (t < 128) ls[t] = 0.f;

    // prologue: group0 = {Q, K(0), V(0)}, group1 = {K(1), V(1)}
    {
        const int j = t >> 2, c = t & 3;
        cpa16(smb + OFF_Q + (j>>1)*128 + (j&1)*64 + c*16,
              g_q + (rowb + j)*CK + c*8);
    }
    copy_kv(smb + OFF_K, smb + OFF_V, t, b, 0);
    CPA_COMMIT();
    copy_kv(smb + OFF_K + KBUF, smb + OFF_V + VBUF, t, b, JT);
    CPA_COMMIT();
    CPA_WAIT(1);          // Q + K(0) + V(0) ready
    __syncthreads();

    uint32_t aq[2][2][4];
    #pragma unroll
    for (int m = 0; m < 2; m++)
        #pragma unroll
        for (int kk = 0; kk < 2; kk++)
            ldsm4(addrA_pk(smb + OFF_Q, rs + 16*m, kk*32, lane), aq[m][kk]);

    float o[2][8][4];
    #pragma unroll
    for (int m = 0; m < 2; m++)
        #pragma unroll
        for (int n = 0; n < 8; n++)
            { o[m][n][0]=0.f; o[m][n][1]=0.f; o[m][n][2]=0.f; o[m][n][3]=0.f; }
    float lr[4] = {0.f, 0.f, 0.f, 0.f};

    // S(0) -> P[0]
    s_phase(smb, 0, aq, rs, cg, lane, lr);

    for (int it = 0; it < NIT; it++) {
        CPA_WAIT(0);       // K/V(it+1) complete
        __syncthreads();   // PV(it-1)/S(it) reads done; copies + P(it) visible

        if (it + 2 < NIT) {   // prefetch K/V(it+2): buffers free (3-deep)
            copy_kv(smb + OFF_K + (uint32_t)((it+2)%3)*KBUF,
                    smb + OFF_V + (uint32_t)((it+2)%3)*VBUF, t, b, (it+2)*JT);
            CPA_COMMIT();
        }

        // ---- S(it+1) -> P[(it+1)&1]  (independent of PV below) ----
        if (it + 1 < NIT)
            s_phase(smb, it+1, aq, rs, cg, lane, lr);

        // ---- PV(it): rows rs..rs+31 x d-quarter, k = JT ----
        const uint32_t pb = smb + OFF_P + (uint32_t)(it & 1)*PBUF;
        const uint32_t vb = smb + OFF_V + (uint32_t)(it % 3)*VBUF;
        #pragma unroll
        for (int j16 = 0; j16 < 4; j16++) {
            uint32_t A0[4], A1[4];
            ldsm4(addrA(pb, rs,      j16*32, 128, lane), A0);
            ldsm4(addrA(pb, rs + 16, j16*32, 128, lane), A1);
            #pragma unroll
            for (int n16 = 0; n16 < 4; n16++) {
                uint32_t Bv[4];
                ldsm4(addrB(vb, dh + n16*16, j16*32, 128, lane), Bv);
                mma_bf16(o[0][n16*2],   A0, Bv[0], Bv[1]);
                mma_bf16(o[0][n16*2+1], A0, Bv[2], Bv[3]);
                mma_bf16(o[1][n16*2],   A1, Bv[0], Bv[1]);
                mma_bf16(o[1][n16*2+1], A1, Bv[2], Bv[3]);
            }
        }
    }

    // ---- row sums: quad shuffles then cross-colgroup smem atomics ----
    #pragma unroll
    for (int i = 0; i < 4; i++) {
        lr[i] += __shfl_xor_sync(0xffffffffu, lr[i], 1);
        lr[i] += __shfl_xor_sync(0xffffffffu, lr[i], 2);
    }
    if ((lane & 3) == 0) {
        const int r = rs + (lane >> 2);
        atomicAdd(&ls[r],      lr[0]);
        atomicAdd(&ls[r + 8],  lr[1]);
        atomicAdd(&ls[r + 16], lr[2]);
        atomicAdd(&ls[r + 24], lr[3]);
    }
    __syncthreads();

    // ---- epilogue: y = gamma * O/l + x ----
    const float gamma = *gamma_p;
    #pragma unroll
    for (int m = 0; m < 2; m++) {
        const int ra = rs + 16*m + (lane >> 2);
        const int rb2 = ra + 8;
        const float ga = gamma / ls[ra];
        const float gb = gamma / ls[rb2];
        #pragma unroll
        for (int n = 0; n < 8; n++) {
            const float* oo = o[m][n];
            const int d = dh + (n>>1)*16 + (n&1)*8 + (lane & 3)*2;
            const size_t ea = (rowb + ra)*CDIM + d;
            const size_t eb = (rowb + rb2)*CDIM + d;
            float2 xa = *(const float2*)(x + ea);
            float2 xb = *(const float2*)(x + eb);
            float2 ya, yb;
            ya.x = fmaf(ga, oo[0], xa.x);
            ya.y = fmaf(ga, oo[1], xa.y);
            yb.x = fmaf(gb, oo[2], xb.x);
            yb.y = fmaf(gb, oo[3], xb.y);
            *(float2*)(out + ea) = ya;
            *(float2*)(out + eb) = yb;
        }
    }
}

// ============================================================================
extern "C" void kernel_launch(void* const* d_in, const int* in_sizes, int n_in,
                              void* d_out, int out_size)
{
    const float* x     = (const float*)d_in[0];
    const float* Wf    = (const float*)d_in[1];
    const float* bf    = (const float*)d_in[2];
    const float* Wg    = (const float*)d_in[3];
    const float* bg    = (const float*)d_in[4];
    const float* Wh    = (const float*)d_in[5];
    const float* bh    = (const float*)d_in[6];
    const float* gamma = (const float*)d_in[7];
    float* out = (float*)d_out;
    (void)in_sizes; (void)n_in; (void)out_size;

    cudaFuncSetAttribute(attn_kernel,
                         cudaFuncAttributeMaxDynamicSharedMemorySize, ATTN_SMEM);
    cudaFuncSetAttribute(proj_kernel,
                         cudaFuncAttributeMaxDynamicSharedMemorySize, PJ_SMEM);

    prep_kernel<<<TOTPIX*CDIM/8/256, 256>>>(x, Wf, Wg, Wh);
    proj_kernel<<<dim3(TOTPIX/128, 5), 256, PJ_SMEM>>>(bf, bg, bh);
    attn_kernel<<<dim3(NPIX/128, NB), 512, ATTN_SMEM>>>(x, gamma, out);
}